// round 3
// baseline (speedup 1.0000x reference)
#include <cuda_runtime.h>
#include <cstdint>
#include <cstddef>

#define PDIM 1100
#define DDIM 1024
#define ODIM 1024
#define NB   16
#define NLBL 5000

// ---------------- scratch (static device globals; no runtime alloc) ----------------
__device__ float g_Pe[NB * DDIM];
__device__ float g_hp[NB * DDIM];        // hp = Pe @ W1_p^T + b1   (b1 folded here)
__device__ float g_Le[NLBL * DDIM];
__device__ float g_hl[NLBL * DDIM];      // hl = Le @ W1_l^T

// ---------------- f32x2 helpers (Blackwell packed FFMA2) ----------------
__device__ __forceinline__ unsigned long long pack_dup(float x) {
    unsigned long long r;
    asm("mov.b64 %0, {%1, %1};" : "=l"(r) : "f"(x));
    return r;
}
__device__ __forceinline__ void ffma2(unsigned long long& d, unsigned long long a,
                                      unsigned long long b) {
    asm("fma.rn.f32x2 %0, %1, %2, %0;" : "+l"(d) : "l"(a), "l"(b));
}
__device__ __forceinline__ float2 unpk(unsigned long long v) {
    float lo, hi;
    asm("mov.b64 {%0, %1}, %2;" : "=f"(lo), "=f"(hi) : "l"(v));
    return make_float2(lo, hi);
}

// ---------------- kernel 1a: Pe[b, :] = seq[b, :] @ Wp^T ----------------
__global__ __launch_bounds__(256) void pe_kernel(const float* __restrict__ seq,
                                                 const float* __restrict__ Wp,
                                                 float* __restrict__ Pe) {
    __shared__ float s[PDIM];
    const int b = blockIdx.x, tid = threadIdx.x;
    for (int i = tid; i < PDIM; i += 256) s[i] = seq[b * PDIM + i];
    __syncthreads();
    const int warp = tid >> 5, lane = tid & 31;
    for (int d = warp; d < DDIM; d += 8) {
        const float* wrow = Wp + (size_t)d * PDIM;
        float p = 0.f;
        for (int k = lane; k < PDIM; k += 32) p = fmaf(s[k], wrow[k], p);
        #pragma unroll
        for (int off = 16; off > 0; off >>= 1) p += __shfl_down_sync(0xffffffffu, p, off);
        if (lane == 0) Pe[b * DDIM + d] = p;
    }
}

// ---------------- kernel 1b: hp[b, :] = Pe[b, :] @ W1_p^T + b1 ----------------
__global__ __launch_bounds__(256) void hp_kernel(const float* __restrict__ Pe,
                                                 const float* __restrict__ W1,
                                                 const float* __restrict__ b1,
                                                 float* __restrict__ hp) {
    __shared__ float s[DDIM];
    const int b = blockIdx.x, tid = threadIdx.x;
    for (int i = tid; i < DDIM; i += 256) s[i] = Pe[b * DDIM + i];
    __syncthreads();
    const int warp = tid >> 5, lane = tid & 31;
    for (int o = warp; o < ODIM; o += 8) {
        const float* wrow = W1 + (size_t)o * (2 * DDIM);  // first (P) half
        float p = 0.f;
        for (int k = lane; k < DDIM; k += 32) p = fmaf(s[k], wrow[k], p);
        #pragma unroll
        for (int off = 16; off > 0; off >>= 1) p += __shfl_down_sync(0xffffffffu, p, off);
        if (lane == 0) hp[b * DDIM + o] = p + b1[o];
    }
}

// ---------------- kernel 2: C[M,1024] = A[M,1024] @ Bm^T (Bm rows stride ldb) ----------------
__global__ __launch_bounds__(256, 2) void gemm128_kernel(const float* __restrict__ A,
                                                         const float* __restrict__ Bm,
                                                         float* __restrict__ C,
                                                         int M, int ldb) {
    __shared__ __align__(16) float Asm[16][130];
    __shared__ __align__(16) float Bsm[16][130];
    const int tid = threadIdx.x;
    const int tx = tid & 15, ty = tid >> 4;
    const int row0 = blockIdx.y * 128;
    const int col0 = blockIdx.x * 128;

    unsigned long long acc[8][4];
    #pragma unroll
    for (int i = 0; i < 8; i++)
        #pragma unroll
        for (int j = 0; j < 4; j++) acc[i][j] = 0ull;

    const int r_st = tid >> 2;
    const int kq = (tid & 3) * 4;

    for (int k0 = 0; k0 < 1024; k0 += 16) {
        #pragma unroll
        for (int pass = 0; pass < 2; pass++) {
            int r = r_st + pass * 64;
            int gr = row0 + r;
            float4 a = make_float4(0.f, 0.f, 0.f, 0.f);
            if (gr < M) a = *(const float4*)(A + (size_t)gr * 1024 + k0 + kq);
            Asm[kq + 0][r] = a.x; Asm[kq + 1][r] = a.y;
            Asm[kq + 2][r] = a.z; Asm[kq + 3][r] = a.w;
            int gc = col0 + r;
            float4 bq = *(const float4*)(Bm + (size_t)gc * ldb + k0 + kq);
            Bsm[kq + 0][r] = bq.x; Bsm[kq + 1][r] = bq.y;
            Bsm[kq + 2][r] = bq.z; Bsm[kq + 3][r] = bq.w;
        }
        __syncthreads();
        #pragma unroll
        for (int kk = 0; kk < 16; kk++) {
            unsigned long long av[8];
            #pragma unroll
            for (int i = 0; i < 8; i++) av[i] = pack_dup(Asm[kk][i * 16 + ty]);
            unsigned long long bv[4];
            #pragma unroll
            for (int j = 0; j < 4; j++)
                bv[j] = *(const unsigned long long*)&Bsm[kk][j * 32 + tx * 2];
            #pragma unroll
            for (int i = 0; i < 8; i++)
                #pragma unroll
                for (int j = 0; j < 4; j++) ffma2(acc[i][j], av[i], bv[j]);
        }
        __syncthreads();
    }
    #pragma unroll
    for (int i = 0; i < 8; i++) {
        int gr = row0 + i * 16 + ty;
        if (gr < M) {
            #pragma unroll
            for (int j = 0; j < 4; j++) {
                float2 v = unpk(acc[i][j]);
                *(float2*)(C + (size_t)gr * 1024 + col0 + j * 32 + tx * 2) = v;
            }
        }
    }
}

// ---------------- kernel 3: fused relu(h) @ W2^T -> relu -> dot W3 ----------------
#define FROWS 32
#define FBK   32
#define WPAD  514
#define FUSED_SMEM_FLOATS (FROWS * DDIM + FBK * WPAD + FROWS)
#define FUSED_SMEM_BYTES  (FUSED_SMEM_FLOATS * 4)

__global__ __launch_bounds__(256, 1) void fused_kernel(const float* __restrict__ hp,
                                                       const float* __restrict__ hl,
                                                       const float* __restrict__ W2,
                                                       const float* __restrict__ b2,
                                                       const float* __restrict__ W3,
                                                       const float* __restrict__ b3,
                                                       float* __restrict__ out) {
    extern __shared__ __align__(16) float sm[];
    float* hsm   = sm;                    // [32][1024]  h tile (post-ReLU)
    float* wsm   = sm + FROWS * DDIM;     // [32][514]   W2 k-tile
    float* logsm = wsm + FBK * WPAD;      // [32]

    const int tid = threadIdx.x;
    const int r0 = blockIdx.x * FROWS;

    // Stage h tile: h[row][k] = relu(hp[b] + hl[l])  (b1 already folded into hp)
    #pragma unroll 4
    for (int row = 0; row < FROWS; ++row) {
        int r = r0 + row;
        int b = r / NLBL;
        int l = r - b * NLBL;
        float4 a = *(const float4*)(hp + (size_t)b * DDIM + tid * 4);
        float4 c = *(const float4*)(hl + (size_t)l * DDIM + tid * 4);
        float4 v;
        v.x = fmaxf(a.x + c.x, 0.f); v.y = fmaxf(a.y + c.y, 0.f);
        v.z = fmaxf(a.z + c.z, 0.f); v.w = fmaxf(a.w + c.w, 0.f);
        *(float4*)(hsm + row * DDIM + tid * 4) = v;
    }
    if (tid < FROWS) logsm[tid] = 0.f;

    const int tx = tid & 63;      // column lane (64)
    const int ty = tid >> 6;      // row group  (4 x 8 rows)
    const int c_st = tid >> 3;    // staging col 0..31
    const int skq = (tid & 7) * 4;

    float part[8];
    #pragma unroll
    for (int i = 0; i < 8; i++) part[i] = 0.f;

    for (int chunk = 0; chunk < 2; ++chunk) {
        const int col0 = chunk * 512;
        unsigned long long acc[8][4];
        #pragma unroll
        for (int i = 0; i < 8; i++)
            #pragma unroll
            for (int j = 0; j < 4; j++) acc[i][j] = 0ull;

        for (int k0 = 0; k0 < DDIM; k0 += FBK) {
            __syncthreads();
            // stage W2[col0..col0+512)[k0..k0+32) transposed -> wsm[kk][col]
            #pragma unroll
            for (int pass = 0; pass < 16; ++pass) {
                int c = c_st + pass * 32;
                float4 w = *(const float4*)(W2 + (size_t)(col0 + c) * DDIM + k0 + skq);
                wsm[(skq + 0) * WPAD + c] = w.x;
                wsm[(skq + 1) * WPAD + c] = w.y;
                wsm[(skq + 2) * WPAD + c] = w.z;
                wsm[(skq + 3) * WPAD + c] = w.w;
            }
            __syncthreads();
            #pragma unroll 8
            for (int kk = 0; kk < FBK; ++kk) {
                unsigned long long hv[8];
                #pragma unroll
                for (int i = 0; i < 8; i++)
                    hv[i] = pack_dup(hsm[(ty * 8 + i) * DDIM + k0 + kk]);
                unsigned long long wv[4];
                #pragma unroll
                for (int j = 0; j < 4; j++)
                    wv[j] = *(const unsigned long long*)&wsm[kk * WPAD + j * 128 + tx * 2];
                #pragma unroll
                for (int i = 0; i < 8; i++)
                    #pragma unroll
                    for (int j = 0; j < 4; j++) ffma2(acc[i][j], hv[i], wv[j]);
            }
        }
        // epilogue for this 512-col chunk: relu(+b2) then dot with W3
        #pragma unroll
        for (int j = 0; j < 4; j++) {
            int col = col0 + j * 128 + tx * 2;
            float2 bb = *(const float2*)(b2 + col);
            float2 w3 = *(const float2*)(W3 + col);
            #pragma unroll
            for (int i = 0; i < 8; i++) {
                float2 v = unpk(acc[i][j]);
                float h0 = fmaxf(v.x + bb.x, 0.f);
                float h1 = fmaxf(v.y + bb.y, 0.f);
                part[i] = fmaf(h0, w3.x, fmaf(h1, w3.y, part[i]));
            }
        }
    }

    // reduce partials over the 64 column lanes (2 warps per row-group)
    #pragma unroll
    for (int i = 0; i < 8; i++) {
        float v = part[i];
        #pragma unroll
        for (int off = 16; off > 0; off >>= 1) v += __shfl_down_sync(0xffffffffu, v, off);
        if ((tid & 31) == 0) atomicAdd(&logsm[ty * 8 + i], v);
    }
    __syncthreads();
    if (tid < FROWS) out[r0 + tid] = logsm[tid] + b3[0];
}

// ---------------- launch ----------------
extern "C" void kernel_launch(void* const* d_in, const int* in_sizes, int n_in,
                              void* d_out, int out_size) {
    const float* seq    = (const float*)d_in[0];
    const float* labels = (const float*)d_in[1];
    const float* Wp     = (const float*)d_in[2];
    const float* Wl     = (const float*)d_in[3];
    const float* W1     = (const float*)d_in[4];
    const float* b1     = (const float*)d_in[5];
    const float* W2     = (const float*)d_in[6];
    const float* b2     = (const float*)d_in[7];
    const float* W3     = (const float*)d_in[8];
    const float* b3     = (const float*)d_in[9];
    float* out = (float*)d_out;

    float *Pe, *hp, *Le, *hl;
    cudaGetSymbolAddress((void**)&Pe, g_Pe);
    cudaGetSymbolAddress((void**)&hp, g_hp);
    cudaGetSymbolAddress((void**)&Le, g_Le);
    cudaGetSymbolAddress((void**)&hl, g_hl);

    pe_kernel<<<NB, 256>>>(seq, Wp, Pe);
    hp_kernel<<<NB, 256>>>(Pe, W1, b1, hp);

    // Le = labels @ Wl^T           (ldb = 1024)
    gemm128_kernel<<<dim3(8, 40), 256>>>(labels, Wl, Le, NLBL, 1024);
    // hl = Le @ W1_l^T   (B = W1 + 1024, row stride 2048)
    gemm128_kernel<<<dim3(8, 40), 256>>>(Le, W1 + DDIM, hl, NLBL, 2 * DDIM);

    cudaFuncSetAttribute(fused_kernel, cudaFuncAttributeMaxDynamicSharedMemorySize,
                         FUSED_SMEM_BYTES);
    fused_kernel<<<(NB * NLBL) / FROWS, 256, FUSED_SMEM_BYTES>>>(hp, hl, W2, b2, W3, b3,
                                                                 out);
}

// round 7
// speedup vs baseline: 1.5521x; 1.5521x over previous
#include <cuda_runtime.h>
#include <cuda_bf16.h>
#include <cstdint>
#include <cstddef>

#define PDIM 1100
#define DDIM 1024
#define ODIM 1024
#define NB   16
#define NLBL 5000

// ---------------- scratch (static device globals; no runtime alloc) ----------------
__device__ float g_Pe[NB * DDIM];
__device__ float g_hp[NB * DDIM];        // hp = Pe @ W1_p^T + b1
__device__ float g_Le[NLBL * DDIM];
__device__ float g_hl[NLBL * DDIM];      // hl = Le @ W1_l^T
__device__ __align__(16) __nv_bfloat16 g_W2h[ODIM * DDIM];
__device__ __align__(16) __nv_bfloat16 g_W2l[ODIM * DDIM];

// ---------------- f32x2 helpers (SIMT gemm128) ----------------
__device__ __forceinline__ unsigned long long pack_dup(float x) {
    unsigned long long r;
    asm("mov.b64 %0, {%1, %1};" : "=l"(r) : "f"(x));
    return r;
}
__device__ __forceinline__ void ffma2(unsigned long long& d, unsigned long long a,
                                      unsigned long long b) {
    asm("fma.rn.f32x2 %0, %1, %2, %0;" : "+l"(d) : "l"(a), "l"(b));
}
__device__ __forceinline__ float2 unpk(unsigned long long v) {
    float lo, hi;
    asm("mov.b64 {%0, %1}, %2;" : "=f"(lo), "=f"(hi) : "l"(v));
    return make_float2(lo, hi);
}

// ---------------- bf16 split helpers ----------------
// result word: low half = bf16(lo_elem), high half = bf16(hi_elem)
__device__ __forceinline__ unsigned pack_bf2(float lo_elem, float hi_elem) {
    unsigned r;
    asm("cvt.rn.bf16x2.f32 %0, %1, %2;" : "=r"(r) : "f"(hi_elem), "f"(lo_elem));
    return r;
}
__device__ __forceinline__ float lo16f(unsigned u) { return __uint_as_float(u << 16); }
__device__ __forceinline__ float hi16f(unsigned u) { return __uint_as_float(u & 0xffff0000u); }

// ---------------- mma.sync m16n8k16 bf16 (standard PTX, base sm_103 target) ----------------
__device__ __forceinline__ void mma16816(float* c, const unsigned* a, const unsigned* b) {
    asm volatile(
        "mma.sync.aligned.m16n8k16.row.col.f32.bf16.bf16.f32 "
        "{%0,%1,%2,%3}, {%4,%5,%6,%7}, {%8,%9}, {%0,%1,%2,%3};"
        : "+f"(c[0]), "+f"(c[1]), "+f"(c[2]), "+f"(c[3])
        : "r"(a[0]), "r"(a[1]), "r"(a[2]), "r"(a[3]), "r"(b[0]), "r"(b[1]));
}

// ---------------- kernel 1a: Pe[b, :] = seq[b, :] @ Wp^T ----------------
__global__ __launch_bounds__(256) void pe_kernel(const float* __restrict__ seq,
                                                 const float* __restrict__ Wp,
                                                 float* __restrict__ Pe) {
    __shared__ float s[PDIM];
    const int b = blockIdx.x, tid = threadIdx.x;
    for (int i = tid; i < PDIM; i += 256) s[i] = seq[b * PDIM + i];
    __syncthreads();
    const int warp = tid >> 5, lane = tid & 31;
    for (int d = warp; d < DDIM; d += 8) {
        const float* wrow = Wp + (size_t)d * PDIM;
        float p = 0.f;
        for (int k = lane; k < PDIM; k += 32) p = fmaf(s[k], wrow[k], p);
        #pragma unroll
        for (int off = 16; off > 0; off >>= 1) p += __shfl_down_sync(0xffffffffu, p, off);
        if (lane == 0) Pe[b * DDIM + d] = p;
    }
}

// ---------------- kernel 1b: hp[b, :] = Pe[b, :] @ W1_p^T + b1 ----------------
__global__ __launch_bounds__(256) void hp_kernel(const float* __restrict__ Pe,
                                                 const float* __restrict__ W1,
                                                 const float* __restrict__ b1,
                                                 float* __restrict__ hp) {
    __shared__ float s[DDIM];
    const int b = blockIdx.x, tid = threadIdx.x;
    for (int i = tid; i < DDIM; i += 256) s[i] = Pe[b * DDIM + i];
    __syncthreads();
    const int warp = tid >> 5, lane = tid & 31;
    for (int o = warp; o < ODIM; o += 8) {
        const float* wrow = W1 + (size_t)o * (2 * DDIM);
        float p = 0.f;
        for (int k = lane; k < DDIM; k += 32) p = fmaf(s[k], wrow[k], p);
        #pragma unroll
        for (int off = 16; off > 0; off >>= 1) p += __shfl_down_sync(0xffffffffu, p, off);
        if (lane == 0) hp[b * DDIM + o] = p + b1[o];
    }
}

// ---------------- kernel 2: SIMT f32x2 GEMM (label-side, fp32-exact) ----------------
__global__ __launch_bounds__(256, 2) void gemm128_kernel(const float* __restrict__ A,
                                                         const float* __restrict__ Bm,
                                                         float* __restrict__ C,
                                                         int M, int ldb) {
    __shared__ __align__(16) float Asm[16][130];
    __shared__ __align__(16) float Bsm[16][130];
    const int tid = threadIdx.x;
    const int tx = tid & 15, ty = tid >> 4;
    const int row0 = blockIdx.y * 128;
    const int col0 = blockIdx.x * 128;

    unsigned long long acc[8][4];
    #pragma unroll
    for (int i = 0; i < 8; i++)
        #pragma unroll
        for (int j = 0; j < 4; j++) acc[i][j] = 0ull;

    const int r_st = tid >> 2;
    const int kq = (tid & 3) * 4;

    for (int k0 = 0; k0 < 1024; k0 += 16) {
        #pragma unroll
        for (int pass = 0; pass < 2; pass++) {
            int r = r_st + pass * 64;
            int gr = row0 + r;
            float4 a = make_float4(0.f, 0.f, 0.f, 0.f);
            if (gr < M) a = *(const float4*)(A + (size_t)gr * 1024 + k0 + kq);
            Asm[kq + 0][r] = a.x; Asm[kq + 1][r] = a.y;
            Asm[kq + 2][r] = a.z; Asm[kq + 3][r] = a.w;
            int gc = col0 + r;
            float4 bq = *(const float4*)(Bm + (size_t)gc * ldb + k0 + kq);
            Bsm[kq + 0][r] = bq.x; Bsm[kq + 1][r] = bq.y;
            Bsm[kq + 2][r] = bq.z; Bsm[kq + 3][r] = bq.w;
        }
        __syncthreads();
        #pragma unroll
        for (int kk = 0; kk < 16; kk++) {
            unsigned long long av[8];
            #pragma unroll
            for (int i = 0; i < 8; i++) av[i] = pack_dup(Asm[kk][i * 16 + ty]);
            unsigned long long bv[4];
            #pragma unroll
            for (int j = 0; j < 4; j++)
                bv[j] = *(const unsigned long long*)&Bsm[kk][j * 32 + tx * 2];
            #pragma unroll
            for (int i = 0; i < 8; i++)
                #pragma unroll
                for (int j = 0; j < 4; j++) ffma2(acc[i][j], av[i], bv[j]);
        }
        __syncthreads();
    }
    #pragma unroll
    for (int i = 0; i < 8; i++) {
        int gr = row0 + i * 16 + ty;
        if (gr < M) {
            #pragma unroll
            for (int j = 0; j < 4; j++) {
                float2 v = unpk(acc[i][j]);
                *(float2*)(C + (size_t)gr * 1024 + col0 + j * 32 + tx * 2) = v;
            }
        }
    }
}

// ---------------- kernel 2b: split W2 into bf16 hi/lo ----------------
__global__ __launch_bounds__(256) void w2split_kernel(const float* __restrict__ W2,
                                                      __nv_bfloat16* __restrict__ Wh,
                                                      __nv_bfloat16* __restrict__ Wl) {
    int i = blockIdx.x * 256 + threadIdx.x;  // one float4 each
    float4 v = ((const float4*)W2)[i];
    unsigned h0 = pack_bf2(v.x, v.y);
    unsigned h1 = pack_bf2(v.z, v.w);
    unsigned l0 = pack_bf2(v.x - lo16f(h0), v.y - hi16f(h0));
    unsigned l1 = pack_bf2(v.z - lo16f(h1), v.w - hi16f(h1));
    ((uint2*)Wh)[i] = make_uint2(h0, h1);
    ((uint2*)Wl)[i] = make_uint2(l0, l1);
}

// ---------------- kernel 3: fused mma.sync bf16x3  relu(h)@W2^T -> relu -> dot W3 ----------------
// CTA: 256 thr (8 warps, 2 M x 4 N), M=128 rows, nt loop over 4 N-tiles of 256,
// K staged 64 wide in smem (h rebuilt + split per chunk). Row stride 72 bf16: LDS
// fragment reads provably bank-conflict-free (36 banks/row).
#define APAD 72
#define SB_AH   0
#define SB_AL   (SB_AH + 128 * APAD * 2)          // 18432
#define SB_BH   (SB_AL + 128 * APAD * 2)          // 36864
#define SB_BL   (SB_BH + 256 * APAD * 2)          // 73728
#define SB_B2   (SB_BL + 256 * APAD * 2)          // 110592
#define SB_W3   (SB_B2 + 4096)
#define SB_LOG  (SB_W3 + 4096)
#define FM_SMEM (SB_LOG + 512)

__global__ __launch_bounds__(256, 1) void fused_mma_kernel(
    const float* __restrict__ hp, const float* __restrict__ hl,
    const __nv_bfloat16* __restrict__ W2h, const __nv_bfloat16* __restrict__ W2l,
    const float* __restrict__ b2, const float* __restrict__ W3,
    const float* __restrict__ b3, float* __restrict__ out) {
    extern __shared__ __align__(16) char smem[];
    __nv_bfloat16* Ah = (__nv_bfloat16*)(smem + SB_AH);
    __nv_bfloat16* Al = (__nv_bfloat16*)(smem + SB_AL);
    __nv_bfloat16* Bh = (__nv_bfloat16*)(smem + SB_BH);
    __nv_bfloat16* Bl = (__nv_bfloat16*)(smem + SB_BL);
    float* b2s    = (float*)(smem + SB_B2);
    float* w3s    = (float*)(smem + SB_W3);
    float* logits = (float*)(smem + SB_LOG);

    const int tid = threadIdx.x;
    const int lane = tid & 31;
    const int wid = tid >> 5;
    const int warp_m = wid & 1;       // 0..1
    const int warp_n = wid >> 1;      // 0..3
    const int gid = lane >> 2;        // 0..7 (row group)
    const int tig = lane & 3;         // 0..3
    const int r0 = blockIdx.x * 128;

    for (int i = tid; i < ODIM; i += 256) { b2s[i] = b2[i]; w3s[i] = W3[i]; }
    if (tid < 128) logits[tid] = 0.f;

    // A-staging mapping: 2 threads per row (32-col halves)
    const int am = tid >> 1;
    const int ahalf = (tid & 1) * 32;
    const int ar = r0 + am;
    const int ab = ar / NLBL;
    const int alr = ar - ab * NLBL;
    const float* hpA = hp + (size_t)ab * DDIM;
    const float* hlA = hl + (size_t)alr * DDIM;

    float pr[8];
    #pragma unroll
    for (int i = 0; i < 8; ++i) pr[i] = 0.f;

    for (int nt = 0; nt < 4; ++nt) {
        float acc[4][8][4];
        #pragma unroll
        for (int mt = 0; mt < 4; ++mt)
            #pragma unroll
            for (int ntl = 0; ntl < 8; ++ntl)
                #pragma unroll
                for (int c = 0; c < 4; ++c) acc[mt][ntl][c] = 0.f;

        for (int kc = 0; kc < 16; ++kc) {
            const int k0 = kc * 64;
            __syncthreads();
            // ---- stage A: h = relu(hp+hl) split hi/lo -> Ah/Al [128][72]
            #pragma unroll
            for (int j = 0; j < 8; ++j) {
                const int k = ahalf + j * 4;
                float4 p = *(const float4*)(hpA + k0 + k);
                float4 q = *(const float4*)(hlA + k0 + k);
                float v0 = fmaxf(p.x + q.x, 0.f), v1 = fmaxf(p.y + q.y, 0.f);
                float v2 = fmaxf(p.z + q.z, 0.f), v3 = fmaxf(p.w + q.w, 0.f);
                unsigned h0 = pack_bf2(v0, v1), h1 = pack_bf2(v2, v3);
                unsigned l0 = pack_bf2(v0 - lo16f(h0), v1 - hi16f(h0));
                unsigned l1 = pack_bf2(v2 - lo16f(h1), v3 - hi16f(h1));
                *(uint2*)((char*)Ah + am * (APAD * 2) + k * 2) = make_uint2(h0, h1);
                *(uint2*)((char*)Al + am * (APAD * 2) + k * 2) = make_uint2(l0, l1);
            }
            // ---- stage B: W2 hi/lo rows -> Bh/Bl [256][72]
            {
                const int n = tid;
                const uint4* sH = (const uint4*)(W2h + (size_t)(nt * 256 + n) * DDIM + k0);
                const uint4* sL = (const uint4*)(W2l + (size_t)(nt * 256 + n) * DDIM + k0);
                #pragma unroll
                for (int g = 0; g < 8; ++g) {
                    uint4 h = sH[g];
                    uint4 l = sL[g];
                    char* dh = (char*)Bh + n * (APAD * 2) + g * 16;
                    char* dl = (char*)Bl + n * (APAD * 2) + g * 16;
                    *(uint2*)dh = make_uint2(h.x, h.y);
                    *(uint2*)(dh + 8) = make_uint2(h.z, h.w);
                    *(uint2*)dl = make_uint2(l.x, l.y);
                    *(uint2*)(dl + 8) = make_uint2(l.z, l.w);
                }
            }
            __syncthreads();
            // ---- mma over 4 k16 steps
            #pragma unroll
            for (int s = 0; s < 4; ++s) {
                const int cb = s * 16 + tig * 2;
                unsigned ahi[4][4], alo[4][4];
                #pragma unroll
                for (int mt = 0; mt < 4; ++mt) {
                    const int r = warp_m * 64 + mt * 16 + gid;
                    ahi[mt][0] = *(const unsigned*)(Ah + r * APAD + cb);
                    ahi[mt][1] = *(const unsigned*)(Ah + (r + 8) * APAD + cb);
                    ahi[mt][2] = *(const unsigned*)(Ah + r * APAD + cb + 8);
                    ahi[mt][3] = *(const unsigned*)(Ah + (r + 8) * APAD + cb + 8);
                    alo[mt][0] = *(const unsigned*)(Al + r * APAD + cb);
                    alo[mt][1] = *(const unsigned*)(Al + (r + 8) * APAD + cb);
                    alo[mt][2] = *(const unsigned*)(Al + r * APAD + cb + 8);
                    alo[mt][3] = *(const unsigned*)(Al + (r + 8) * APAD + cb + 8);
                }
                #pragma unroll
                for (int ntl = 0; ntl < 8; ++ntl) {
                    const int n = warp_n * 64 + ntl * 8 + gid;
                    unsigned bh[2], bl[2];
                    bh[0] = *(const unsigned*)(Bh + n * APAD + cb);
                    bh[1] = *(const unsigned*)(Bh + n * APAD + cb + 8);
                    bl[0] = *(const unsigned*)(Bl + n * APAD + cb);
                    bl[1] = *(const unsigned*)(Bl + n * APAD + cb + 8);
                    #pragma unroll
                    for (int mt = 0; mt < 4; ++mt) mma16816(acc[mt][ntl], ahi[mt], bh);
                    #pragma unroll
                    for (int mt = 0; mt < 4; ++mt) mma16816(acc[mt][ntl], alo[mt], bh);
                    #pragma unroll
                    for (int mt = 0; mt < 4; ++mt) mma16816(acc[mt][ntl], ahi[mt], bl);
                }
            }
        }
        // ---- fold this N-tile: relu(acc + b2) * W3 into per-row partials
        #pragma unroll
        for (int mt = 0; mt < 4; ++mt)
            #pragma unroll
            for (int ntl = 0; ntl < 8; ++ntl) {
                const int colb = nt * 256 + warp_n * 64 + ntl * 8 + tig * 2;
                #pragma unroll
                for (int c = 0; c < 4; ++c) {
                    const int cc = colb + (c & 1);
                    float v = acc[mt][ntl][c] + b2s[cc];
                    pr[mt * 2 + (c >> 1)] =
                        fmaf(fmaxf(v, 0.f), w3s[cc], pr[mt * 2 + (c >> 1)]);
                }
            }
    }

    // reduce over lane quads, then across the 4 N-warps via smem atomics
    #pragma unroll
    for (int i = 0; i < 8; ++i) {
        float v = pr[i];
        v += __shfl_xor_sync(0xffffffffu, v, 1);
        v += __shfl_xor_sync(0xffffffffu, v, 2);
        if ((lane & 3) == 0)
            atomicAdd(&logits[warp_m * 64 + (i >> 1) * 16 + (i & 1) * 8 + gid], v);
    }
    __syncthreads();
    if (tid < 128) out[r0 + tid] = logits[tid] + b3[0];
}

// ---------------- launch ----------------
extern "C" void kernel_launch(void* const* d_in, const int* in_sizes, int n_in,
                              void* d_out, int out_size) {
    const float* seq    = (const float*)d_in[0];
    const float* labels = (const float*)d_in[1];
    const float* Wp     = (const float*)d_in[2];
    const float* Wl     = (const float*)d_in[3];
    const float* W1     = (const float*)d_in[4];
    const float* b1     = (const float*)d_in[5];
    const float* W2     = (const float*)d_in[6];
    const float* b2     = (const float*)d_in[7];
    const float* W3     = (const float*)d_in[8];
    const float* b3     = (const float*)d_in[9];
    float* out = (float*)d_out;

    float *Pe, *hp, *Le, *hl;
    __nv_bfloat16 *W2h, *W2l;
    cudaGetSymbolAddress((void**)&Pe, g_Pe);
    cudaGetSymbolAddress((void**)&hp, g_hp);
    cudaGetSymbolAddress((void**)&Le, g_Le);
    cudaGetSymbolAddress((void**)&hl, g_hl);
    cudaGetSymbolAddress((void**)&W2h, g_W2h);
    cudaGetSymbolAddress((void**)&W2l, g_W2l);

    pe_kernel<<<NB, 256>>>(seq, Wp, Pe);
    hp_kernel<<<NB, 256>>>(Pe, W1, b1, hp);

    // Le = labels @ Wl^T ; hl = Le @ W1_l^T   (fp32-exact SIMT)
    gemm128_kernel<<<dim3(8, 40), 256>>>(labels, Wl, Le, NLBL, 1024);
    gemm128_kernel<<<dim3(8, 40), 256>>>(Le, W1 + DDIM, hl, NLBL, 2 * DDIM);

    // W2 -> bf16 hi/lo
    w2split_kernel<<<(ODIM * DDIM / 4) / 256, 256>>>(W2, W2h, W2l);

    cudaFuncSetAttribute(fused_mma_kernel, cudaFuncAttributeMaxDynamicSharedMemorySize,
                         FM_SMEM);
    fused_mma_kernel<<<(NB * NLBL) / 128, 256, FM_SMEM>>>(hp, hl, W2h, W2l, b2, W3, b3,
                                                          out);
}